// round 9
// baseline (speedup 1.0000x reference)
#include <cuda_runtime.h>
#include <cooperative_groups.h>

namespace cg = cooperative_groups;

// SoftMSMLoss: soft-MSM DP, gamma=1, c=1, 512x512, B=64.
// Probability-domain wavefront (P = e^{-C} as (mantissa, int exp)), hard sign
// gate with exact rare-path fallback. 2-CTA cluster per problem (256 rows
// each), DSMEM push handoff of the boundary row; 1 row/thread, 8 warps/CTA.

#define TLEN 512
#define NWARP 8
#define NBATCH 64
#define CHUNK 8
#define GCHUNK 16
#define NSTEP 544
#define LOG2E 1.4426950408889634f
#define LN2 0.6931471805599453f
#define KCONST 0.36787944117144233f  // e^{-c}, c=1
#define SENT (-(1 << 28))
#define GATE_T 1e-3f

__device__ float g_costs[NBATCH];
__device__ int g_done;

__device__ __forceinline__ float scale2(int d) {  // 2^d, d<=0, underflow->0
    int bb = 127 + d;
    bb = max(bb, 0);
    return __int_as_float(bb << 23);
}

__global__ __launch_bounds__(256, 1) __cluster_dims__(2, 1, 1)
void soft_msm_kernel(const float* __restrict__ x, const float* __restrict__ y,
                     float* __restrict__ out) {
    __shared__ float4 scol[TLEN];  // {y_j, dyb_j, Eb_j, K*Eb_j}
    __shared__ float hand_s[NWARP - 1][TLEN];
    __shared__ int hand_m[NWARP - 1][TLEN];
    __shared__ volatile int flags[NWARP - 1];
    __shared__ float gh_s[TLEN];  // cross-CTA boundary (rank1's copy)
    __shared__ int gh_m[TLEN];
    __shared__ int ghflag;

    cg::cluster_group cluster = cg::this_cluster();
    const int rank = (int)cluster.block_rank();

    const int t = threadIdx.x;  // 0..255
    const int w = t >> 5;
    const int l = t & 31;
    const int b = blockIdx.x >> 1;
    const int row = rank * 256 + t;
    const float* xb = x + b * TLEN;
    const float* yb = y + b * TLEN;

    if (t < NWARP - 1) flags[t] = 0;
    if (t == 0) ghflag = 0;
    for (int jj = t; jj < TLEN; jj += 256) {
        const float yv = yb[jj];
        if (jj > 0) {
            const float dyb = yv - yb[jj - 1];
            const float eb = exp2f(-LOG2E * dyb * dyb);
            scol[jj] = make_float4(yv, dyb, eb, eb * KCONST);
        } else {
            scol[jj] = make_float4(yv, 1e9f, 0.0f, 0.0f);
        }
    }
    const float xi = xb[row];
    float myDxa, myEa, myEaK;
    if (row > 0) {
        myDxa = xi - xb[row - 1];
        myEa = exp2f(-LOG2E * myDxa * myDxa);
        myEaK = myEa * KCONST;
    } else {
        myDxa = 1e9f;
        myEa = 0.0f;
        myEaK = 0.0f;
    }
    __syncthreads();
    cluster.sync();  // rank1's gh/ghflag ready before rank0 pushes

    float* remGHs = (float*)cluster.map_shared_rank((void*)gh_s, 1);
    int* remGHm = (int*)cluster.map_shared_rank((void*)gh_m, 1);
    int* remFlag = (int*)cluster.map_shared_rank((void*)&ghflag, 1);

    float svC = 0.0f;  // own P(row, j-1) mantissa
    int miC = SENT;
    float svD = (row == 0) ? 1.0f : 0.0f;  // rolling up -> diag
    int miD_ = (row == 0) ? 0 : SENT;
    const bool isT0 = (row == 0);
    const bool isCons = (l == 0) && (w > 0);
    const bool crossCons = (rank == 1) && (w == 0) && (l == 0);
    const bool crossPollW = (rank == 1) && (w == 0);
    const bool isProd = (l == 31) && (w < NWARP - 1);
    const bool gProd = (rank == 0) && (t == 255);
    int availS = 0, availG = 0;

#pragma unroll 8
    for (int s = 0; s < NSTEP; ++s) {
        if (crossPollW && s < TLEN && (s & (GCHUNK - 1)) == 0) {
            const int need = s + GCHUNK;  // <= TLEN
            if (availG < need) {
                while ((availG = *(volatile int*)&ghflag) < need)
                    __nanosleep(20);
                asm volatile("fence.acq_rel.cluster;" ::: "memory");
            }
        }
        if (w > 0 && s < TLEN && (s & (CHUNK - 1)) == 0) {
            int need = s + CHUNK;
            if (need > TLEN) need = TLEN;
            if (availS < need) {
                while ((availS = flags[w - 1]) < need) __nanosleep(20);
                __threadfence_block();
            }
        }

        float svU = __shfl_up_sync(0xffffffffu, svC, 1);
        int miU = __shfl_up_sync(0xffffffffu, miC, 1);
        const int j = s - l;
        const bool active = ((unsigned)j < (unsigned)TLEN);
        const int jc = active ? j : 0;
        if (isT0) { svU = 0.0f; miU = SENT; }
        if (isCons) { svU = hand_s[w - 1][jc]; miU = hand_m[w - 1][jc]; }
        if (crossCons) { svU = gh_s[jc]; miU = gh_m[jc]; }
        const float dgS = svD;
        const int dgM = miD_;
        svD = svU;
        miD_ = miU;

        const float4 cv = scol[jc];
        const float bm = xi - cv.x;
        const float matchp = (LOG2E * bm) * bm;
        const float Em = exp2f(-matchp);
        const float EmK = Em * KCONST;

        const float uu = myDxa * bm;
        const float ul = -cv.y * bm;
        float selU = (uu > 0.0f) ? (myEaK + EmK) : KCONST;
        float selL = (ul > 0.0f) ? (cv.w + EmK) : KCONST;
        if (fabsf(uu) < GATE_T || fabsf(ul) < GATE_T) {  // exact smooth gate
            const float wu = 0.5f + 0.5f * uu * rsqrtf(uu * uu + 1e-9f);
            selU = KCONST * exp2f(wu * __log2f(myEa + Em));
            const float wl = 0.5f + 0.5f * ul * rsqrtf(ul * ul + 1e-9f);
            selL = KCONST * exp2f(wl * __log2f(cv.z + Em));
        }

        const float tD = dgS * Em;
        const float tU = svU * selU;
        const float tL = svC * selL;
        const int mh = max(dgM, max(miU, miC));
        const float ssum =
            fmaf(tD, scale2(dgM - mh),
                 fmaf(tU, scale2(miU - mh), tL * scale2(miC - mh)));
        const int sb = __float_as_int(ssum);
        const float svN = __int_as_float((sb & 0x007FFFFF) | 0x3F800000);
        const int miN = mh + ((sb >> 23) - 127);
        if (active) { svC = svN; miC = miN; }

        if (isProd) { hand_s[w][jc] = svC; hand_m[w][jc] = miC; }
        if (isProd && active && ((j & (CHUNK - 1)) == CHUNK - 1)) {
            __threadfence_block();
            flags[w] = j + 1;
        }
        if (gProd && active) {  // DSMEM push, off the critical chain
            remGHs[j] = svC;
            remGHm[j] = miC;
        }
        if (gProd && active && ((j & (GCHUNK - 1)) == GCHUNK - 1)) {
            asm volatile("fence.acq_rel.cluster;" ::: "memory");
            *(volatile int*)remFlag = j + 1;
        }
    }

    cluster.sync();  // DSMEM lifetime: rank0 idles until rank1 drains

    if (rank == 1 && t == 255) {  // global row 511: C = -(mi+log2(sv))*ln2
        g_costs[b] = -((float)miC + __log2f(svC)) * LN2;
        __threadfence();
        const int old = atomicAdd(&g_done, 1);
        if (old == NBATCH - 1) {
            __threadfence();
            float v = 0.0f;
#pragma unroll
            for (int i = 0; i < NBATCH; ++i) v += g_costs[i];
            out[0] = v * (1.0f / (float)NBATCH);
            atomicExch(&g_done, 0);
        }
    }
}

extern "C" void kernel_launch(void* const* d_in, const int* in_sizes, int n_in,
                              void* d_out, int out_size) {
    const float* x = (const float*)d_in[0];
    const float* y = (const float*)d_in[1];
    float* out = (float*)d_out;
    soft_msm_kernel<<<2 * NBATCH, 256>>>(x, y, out);
}

// round 11
// speedup vs baseline: 1.7869x; 1.7869x over previous
#include <cuda_runtime.h>

// SoftMSMLoss: soft-MSM DP, gamma=1, c=1, 512x512, B=64.
// Probability-domain wavefront (P = e^{-C} as (mantissa, int exp) per element,
// the scheme validated in R7/R8). TWO problems per 512-thread block: warps 0-7
// = problem A, warps 8-15 = problem B; each side is R8's 2-rows/thread
// pipeline. 4 warps/SMSP restores issue efficiency. Handoff packed to 32 bits.

#define TLEN 512
#define NWARPS 8  // warps per side
#define NBATCH 64
#define CHUNK 8
#define NSTEP 544
#define LOG2E 1.4426950408889634f
#define LN2 0.6931471805599453f
#define KCONST 0.36787944117144233f  // e^{-c}, c=1
#define SENT (-8192)                 // exponent sentinel for P=0 (fits pack)
#define EXPBIAS 16384
#define GATE_T 1e-3f

__device__ float g_costs[NBATCH];
__device__ int g_done;

__device__ __forceinline__ float scale2(int d) {  // 2^d, d<=0, underflow->0
    int bb = 127 + d;
    bb = max(bb, 0);
    return __int_as_float(bb << 23);
}

// pack sv in [1,2) (top 16 mantissa bits) + 16-bit biased exponent
__device__ __forceinline__ unsigned packp(float sv, int mi) {
    const unsigned frac = (__float_as_uint(sv) >> 7) & 0xFFFFu;
    return (frac << 16) | (unsigned)(mi + EXPBIAS);
}
__device__ __forceinline__ void unpackp(unsigned pk, float& sv, int& mi) {
    sv = __uint_as_float(0x3F800000u | ((pk & 0xFFFF0000u) >> 9));
    mi = (int)(pk & 0xFFFFu) - EXPBIAS;
}

struct PV { float sv; int mi; };

__device__ __forceinline__ PV cell(float svU, int miU, float svD, int miD,
                                   float svL, int miL, float xi, float dxa,
                                   float Ea, float EaK, float4 cv) {
    const float bm = xi - cv.x;
    const float matchp = (LOG2E * bm) * bm;
    const float Em = exp2f(-matchp);
    const float EmK = Em * KCONST;

    const float uu = dxa * bm;
    const float ul = -cv.y * bm;
    float selU = (uu > 0.0f) ? (EaK + EmK) : KCONST;
    float selL = (ul > 0.0f) ? (cv.w + EmK) : KCONST;
    if (fabsf(uu) < GATE_T || fabsf(ul) < GATE_T) {  // exact smooth gate
        const float wu = 0.5f + 0.5f * uu * rsqrtf(uu * uu + 1e-9f);
        selU = KCONST * exp2f(wu * __log2f(Ea + Em));
        const float wl = 0.5f + 0.5f * ul * rsqrtf(ul * ul + 1e-9f);
        selL = KCONST * exp2f(wl * __log2f(cv.z + Em));
    }

    const float tD = svD * Em;
    const float tU = svU * selU;
    const float tL = svL * selL;
    const int mh = max(miD, max(miU, miL));
    const float ssum = fmaf(tD, scale2(miD - mh),
                            fmaf(tU, scale2(miU - mh), tL * scale2(miL - mh)));
    const int sb = __float_as_int(ssum);
    PV r;
    r.sv = __int_as_float((sb & 0x007FFFFF) | 0x3F800000);
    r.mi = mh + ((sb >> 23) - 127);
    return r;
}

__global__ __launch_bounds__(512, 1) void soft_msm_kernel(
    const float* __restrict__ x, const float* __restrict__ y,
    float* __restrict__ out) {
    __shared__ float4 scol[2][TLEN];  // {y_j, dyb_j, Eb_j, K*Eb_j} per side
    __shared__ unsigned hand_p[2][NWARPS - 1][TLEN];
    __shared__ volatile int flags[2][NWARPS - 1];

    const int t = threadIdx.x;
    const int side = t >> 8;   // 0: problem A, 1: problem B
    const int st = t & 255;    // thread within side; owns rows 2st, 2st+1
    const int w = st >> 5;     // warp within side (0..7)
    const int l = st & 31;
    const int p = 2 * blockIdx.x + side;
    const float* xb = x + p * TLEN;
    const float* yb = y + p * TLEN;

    if (st < NWARPS - 1) flags[side][st] = 0;
    for (int jj = st; jj < TLEN; jj += 256) {
        const float yv = yb[jj];
        if (jj > 0) {
            const float dyb = yv - yb[jj - 1];
            const float eb = exp2f(-LOG2E * dyb * dyb);
            scol[side][jj] = make_float4(yv, dyb, eb, eb * KCONST);
        } else {
            scol[side][jj] = make_float4(yv, 1e9f, 0.0f, 0.0f);
        }
    }
    const int r0 = 2 * st, r1 = 2 * st + 1;
    const float xi0 = xb[r0], xi1 = xb[r1];
    float dxa0, Ea0, Ea0K;
    if (r0 > 0) {
        dxa0 = xi0 - xb[r0 - 1];
        Ea0 = exp2f(-LOG2E * dxa0 * dxa0);
        Ea0K = Ea0 * KCONST;
    } else {
        dxa0 = 1e9f; Ea0 = 0.0f; Ea0K = 0.0f;
    }
    const float dxa1 = xi1 - xi0;
    const float Ea1 = exp2f(-LOG2E * dxa1 * dxa1);
    const float Ea1K = Ea1 * KCONST;
    __syncthreads();

    float svC0 = 0.0f, svC1 = 0.0f;  // P(r, j-1)
    int miC0 = SENT, miC1 = SENT;
    float svD0 = (st == 0) ? 1.0f : 0.0f;  // rolling up->diag for row0
    int miD0 = (st == 0) ? 0 : SENT;
    const bool isT0 = (st == 0);
    const bool isCons = (l == 0) && (w > 0);
    const bool isProd = (l == 31) && (w < NWARPS - 1);
    int availS = 0;

#pragma unroll 8
    for (int s = 0; s < NSTEP; ++s) {
        if (w > 0 && s < TLEN && (s & (CHUNK - 1)) == 0) {
            int need = s + CHUNK;
            if (need > TLEN) need = TLEN;
            if (availS < need) {
                while ((availS = flags[side][w - 1]) < need) __nanosleep(20);
                __threadfence_block();
            }
        }

        float svU0 = __shfl_up_sync(0xffffffffu, svC1, 1);  // row above r0
        int miU0 = __shfl_up_sync(0xffffffffu, miC1, 1);
        const int j = s - l;
        const bool active = ((unsigned)j < (unsigned)TLEN);
        const int jc = active ? j : 0;
        if (isT0) { svU0 = 0.0f; miU0 = SENT; }
        if (isCons) unpackp(hand_p[side][w - 1][jc], svU0, miU0);
        const float dg0s = svD0;
        const int dg0m = miD0;
        svD0 = svU0;
        miD0 = miU0;

        const float4 cv = scol[side][jc];
        const PV n0 = cell(svU0, miU0, dg0s, dg0m, svC0, miC0,
                           xi0, dxa0, Ea0, Ea0K, cv);
        const PV n1 = cell(n0.sv, n0.mi, svC0, miC0, svC1, miC1,
                           xi1, dxa1, Ea1, Ea1K, cv);
        if (active) {
            svC0 = n0.sv; miC0 = n0.mi;
            svC1 = n1.sv; miC1 = n1.mi;
        }

        if (isProd) hand_p[side][w][jc] = packp(svC1, miC1);
        if (isProd && active && ((j & (CHUNK - 1)) == CHUNK - 1)) {
            __threadfence_block();
            flags[side][w] = j + 1;
        }
    }

    if (st == 255) {  // row 511 final: C = -(mi + log2(sv)) * ln2
        g_costs[p] = -((float)miC1 + __log2f(svC1)) * LN2;
        __threadfence();
        const int old = atomicAdd(&g_done, 1);
        if (old == NBATCH - 1) {
            __threadfence();
            float v = 0.0f;
#pragma unroll
            for (int i = 0; i < NBATCH; ++i) v += g_costs[i];
            out[0] = v * (1.0f / (float)NBATCH);
            atomicExch(&g_done, 0);
        }
    }
}

extern "C" void kernel_launch(void* const* d_in, const int* in_sizes, int n_in,
                              void* d_out, int out_size) {
    const float* x = (const float*)d_in[0];
    const float* y = (const float*)d_in[1];
    float* out = (float*)d_out;
    soft_msm_kernel<<<NBATCH / 2, 512>>>(x, y, out);
}